// round 1
// baseline (speedup 1.0000x reference)
#include <cuda_runtime.h>
#include <math_constants.h>

#define N_ROWS (64 * 64 * 64)   // 262144 rows
#define D      64
#define KC     512
#define TPB    256
#define NBLK   (N_ROWS / TPB)   // 1024 blocks

// dynamic smem: embeddings [KC*D] + norms [KC]
#define SMEM_BYTES ((KC * D + KC) * (int)sizeof(float))

__device__ float g_block_sums[NBLK];

// ---- packed f32x2 helpers (Blackwell FFMA2 path, PTX-only) ----
__device__ __forceinline__ unsigned long long pack_f32x2(float lo, float hi) {
    unsigned long long r;
    asm("mov.b64 %0, {%1, %2};" : "=l"(r) : "f"(lo), "f"(hi));
    return r;
}
__device__ __forceinline__ void unpack_f32x2(float& lo, float& hi, unsigned long long v) {
    asm("mov.b64 {%0, %1}, %2;" : "=f"(lo), "=f"(hi) : "l"(v));
}
__device__ __forceinline__ unsigned long long fma2(unsigned long long a,
                                                   unsigned long long b,
                                                   unsigned long long c) {
    unsigned long long d;
    asm("fma.rn.f32x2 %0, %1, %2, %3;" : "=l"(d) : "l"(a), "l"(b), "l"(c));
    return d;
}
__device__ __forceinline__ unsigned long long add2(unsigned long long a,
                                                   unsigned long long b) {
    unsigned long long d;
    asm("add.rn.f32x2 %0, %1, %2;" : "=l"(d) : "l"(a), "l"(b));
    return d;
}

__global__ void __launch_bounds__(TPB, 1)
vq_main(const float* __restrict__ x, const float* __restrict__ emb,
        float* __restrict__ out) {
    extern __shared__ float smem[];
    float* sE = smem;            // [KC*D]
    float* sN = smem + KC * D;   // [KC]

    const int tid = threadIdx.x;

    // cooperative load of all embeddings into smem (coalesced float4)
    {
        const float4* e4 = (const float4*)emb;
        float4* s4 = (float4*)sE;
        #pragma unroll
        for (int i = tid; i < KC * D / 4; i += TPB) s4[i] = e4[i];
    }
    __syncthreads();

    // per-code squared norms
    for (int k = tid; k < KC; k += TPB) {
        const float* e = sE + k * D;
        float s = 0.f;
        #pragma unroll
        for (int d = 0; d < D; d++) s += e[d] * e[d];
        sN[k] = s;
    }
    __syncthreads();

    const int row = blockIdx.x * TPB + tid;
    const float4* xr = (const float4*)(x + (size_t)row * D);

    // load row, compute rowsq, pack into f32x2 pairs
    unsigned long long xp[D / 2];
    float rowsq = 0.f;
    #pragma unroll
    for (int i = 0; i < D / 4; i++) {
        float4 v = xr[i];
        rowsq += v.x * v.x + v.y * v.y + v.z * v.z + v.w * v.w;
        xp[2 * i]     = pack_f32x2(v.x, v.y);
        xp[2 * i + 1] = pack_f32x2(v.z, v.w);
    }

    float best = CUDART_INF_F;
    int bestk = 0;

    #pragma unroll 2
    for (int k = 0; k < KC; k++) {
        const ulonglong2* ep = (const ulonglong2*)(sE + k * D);  // broadcast LDS.128
        unsigned long long a0 = 0ull, a1 = 0ull, a2 = 0ull, a3 = 0ull;
        #pragma unroll
        for (int j = 0; j < D / 4; j += 4) {   // 16 ulonglong2 per row -> 4 per acc
            ulonglong2 e0 = ep[j + 0];
            ulonglong2 e1 = ep[j + 1];
            ulonglong2 e2 = ep[j + 2];
            ulonglong2 e3 = ep[j + 3];
            a0 = fma2(xp[2 * (j + 0)], e0.x, a0);
            a0 = fma2(xp[2 * (j + 0) + 1], e0.y, a0);
            a1 = fma2(xp[2 * (j + 1)], e1.x, a1);
            a1 = fma2(xp[2 * (j + 1) + 1], e1.y, a1);
            a2 = fma2(xp[2 * (j + 2)], e2.x, a2);
            a2 = fma2(xp[2 * (j + 2) + 1], e2.y, a2);
            a3 = fma2(xp[2 * (j + 3)], e3.x, a3);
            a3 = fma2(xp[2 * (j + 3) + 1], e3.y, a3);
        }
        a0 = add2(a0, a1);
        a2 = add2(a2, a3);
        a0 = add2(a0, a2);
        float lo, hi;
        unpack_f32x2(lo, hi, a0);
        float dot = lo + hi;

        // replicate reference rounding: (rowsq + ||e||^2) - 2*dot
        float t = rowsq + sN[k];
        float s = t - 2.0f * dot;
        if (s < best) { best = s; bestk = k; }   // strict <: first-index argmin
    }

    // write quantized row + accumulate squared diff for the losses
    const float4* eb = (const float4*)(sE + bestk * D);
    float4* orow = (float4*)(out + (size_t)row * D);
    float diffsq = 0.f;
    #pragma unroll
    for (int i = 0; i < D / 4; i++) {
        float4 e = eb[i];
        orow[i] = e;
        float xa, xb, xc, xd;
        unpack_f32x2(xa, xb, xp[2 * i]);
        unpack_f32x2(xc, xd, xp[2 * i + 1]);
        float d0 = xa - e.x, d1 = xb - e.y, d2 = xc - e.z, d3 = xd - e.w;
        diffsq += d0 * d0 + d1 * d1 + d2 * d2 + d3 * d3;
    }

    // deterministic block reduction
    #pragma unroll
    for (int off = 16; off > 0; off >>= 1)
        diffsq += __shfl_down_sync(0xffffffffu, diffsq, off);
    __shared__ float wsum[TPB / 32];
    if ((tid & 31) == 0) wsum[tid >> 5] = diffsq;
    __syncthreads();
    if (tid == 0) {
        float t = 0.f;
        #pragma unroll
        for (int w = 0; w < TPB / 32; w++) t += wsum[w];
        g_block_sums[blockIdx.x] = t;
    }
}

__global__ void vq_finalize(float* __restrict__ out, int out_size) {
    __shared__ float sh[256];
    const int tid = threadIdx.x;
    float s = 0.f;
    for (int i = tid; i < NBLK; i += 256) s += g_block_sums[i];
    sh[tid] = s;
    __syncthreads();
    for (int off = 128; off > 0; off >>= 1) {
        if (tid < off) sh[tid] += sh[tid + off];
        __syncthreads();
    }
    if (tid == 0) {
        float mean = sh[0] / (float)((long long)N_ROWS * D);
        out[out_size - 2] = mean;          // codebook_loss
        out[out_size - 1] = 0.25f * mean;  // commitment_loss (BETA = 0.25)
    }
}

extern "C" void kernel_launch(void* const* d_in, const int* in_sizes, int n_in,
                              void* d_out, int out_size) {
    const float* x = (const float*)d_in[0];     // inputs (B,H,W,D) f32
    const float* emb = (const float*)d_in[1];   // embeddings (K,D) f32
    float* out = (float*)d_out;

    cudaFuncSetAttribute(vq_main, cudaFuncAttributeMaxDynamicSharedMemorySize,
                         SMEM_BYTES);
    vq_main<<<NBLK, TPB, SMEM_BYTES>>>(x, emb, out);
    vq_finalize<<<1, 256>>>(out, out_size);
}

// round 6
// speedup vs baseline: 1.6538x; 1.6538x over previous
#include <cuda_runtime.h>
#include <cstdint>
#include <math_constants.h>

#define D        64
#define KC       512
#define KHALF    256
#define CHUNKS   32          // 8 codes per chunk, per phase
#define MT       128         // rows per tile
#define TILES    2048        // 262144 / 128
#define NROWS    262144
#define TPB      256
#define GRID     148
#define XSTRIDE  68          // padded row stride (floats) -> conflict-free frags

// ---- smem layout (float offsets) ----
#define OFF_XHI   0
#define OFF_XLO   (MT * XSTRIDE)                 // 8704
#define OFF_EHI   (OFF_XLO + MT * XSTRIDE)       // 17408 (Epack hi: 4096 float4)
#define OFF_ELO   (OFF_EHI + 16384)              // Epack lo
#define OFF_NRM   (OFF_ELO + 16384)
#define OFF_RSQ   (OFF_NRM + KHALF)
#define OFF_BEST  (OFF_RSQ + MT)
#define OFF_BK    (OFF_BEST + MT)
#define OFF_WSUM  (OFF_BK + MT)
#define SM_FLOATS (OFF_WSUM + 8)
#define SM_BYTES  (SM_FLOATS * 4)                // ~203 KB

__device__ float g_best[NROWS];
__device__ int   g_bestk[NROWS];
__device__ float g_cta[GRID];

// tf32 destination must be a .b32 register in PTX (NOT .f32) — that was the
// round-3 compile failure. Returns the tf32-rounded value as an f32 bit pattern.
__device__ __forceinline__ float to_tf32(float v) {
    uint32_t u;
    asm("cvt.rn.tf32.f32 %0, %1;" : "=r"(u) : "f"(v));
    return __uint_as_float(u);
}

// m16n8k8 tf32 mma: C(16x8,f32) += A(16x8) * B(8x8)
__device__ __forceinline__ void mma_tf32(float& c0, float& c1, float& c2, float& c3,
                                         float a0, float a1, float a2, float a3,
                                         float b0, float b1) {
    asm volatile(
        "mma.sync.aligned.m16n8k8.row.col.f32.tf32.tf32.f32 "
        "{%0,%1,%2,%3}, {%4,%5,%6,%7}, {%8,%9}, {%0,%1,%2,%3};"
        : "+f"(c0), "+f"(c1), "+f"(c2), "+f"(c3)
        : "r"(__float_as_uint(a0)), "r"(__float_as_uint(a1)),
          "r"(__float_as_uint(a2)), "r"(__float_as_uint(a3)),
          "r"(__float_as_uint(b0)), "r"(__float_as_uint(b1)));
}

__global__ void __launch_bounds__(TPB, 1)
vq_main(const float* __restrict__ x, const float* __restrict__ emb,
        float* __restrict__ out) {
    extern __shared__ float sm[];
    const int tid  = threadIdx.x;
    const int wid  = tid >> 5;
    const int lane = tid & 31;
    const int g    = lane >> 2;   // groupID
    const int tig  = lane & 3;    // thread-in-group

    float4* EH4 = (float4*)&sm[OFF_EHI];
    float4* EL4 = (float4*)&sm[OFF_ELO];
    int*    sBk = (int*)&sm[OFF_BK];

    float ctaAcc = 0.f;

    for (int phase = 0; phase < 2; phase++) {
        const int kb = phase * KHALF;

        // ---- build E fragment-pack (hi/lo tf32) for this half ----
        // slot = (chunk n, s2 = kstep pair, lane l); float4 = (b0_s, b1_s, b0_s+1, b1_s+1)
        for (int slot = tid; slot < CHUNKS * 4 * 32; slot += TPB) {
            const int n  = slot >> 7;
            const int s2 = (slot >> 5) & 3;
            const int l  = slot & 31;
            const int lg = l >> 2, lt = l & 3;
            const float* er = emb + (size_t)(kb + n * 8 + lg) * D;
            const int c0 = 16 * s2 + lt;
            float v0 = er[c0], v1 = er[c0 + 4], v2 = er[c0 + 8], v3 = er[c0 + 12];
            float h0 = to_tf32(v0), h1 = to_tf32(v1), h2 = to_tf32(v2), h3 = to_tf32(v3);
            EH4[slot] = make_float4(h0, h1, h2, h3);
            EL4[slot] = make_float4(to_tf32(v0 - h0), to_tf32(v1 - h1),
                                    to_tf32(v2 - h2), to_tf32(v3 - h3));
        }
        // per-code norms, round-1 summation order (left-to-right scalar)
        {
            const float* er = emb + (size_t)(kb + tid) * D;
            float s = 0.f;
            #pragma unroll
            for (int d = 0; d < D; d++) s += er[d] * er[d];
            sm[OFF_NRM + tid] = s;
        }
        __syncthreads();

        for (int t = blockIdx.x; t < TILES; t += GRID) {
            const float4* xb = (const float4*)(x + (size_t)t * (MT * D));

            // ---- build X tile hi/lo (padded, stride 68) ----
            #pragma unroll
            for (int it = 0; it < 8; it++) {
                const int i = it * TPB + tid;
                float4 v = xb[i];
                const int r = i >> 4, c4 = i & 15;
                float4 h, l;
                h.x = to_tf32(v.x); h.y = to_tf32(v.y);
                h.z = to_tf32(v.z); h.w = to_tf32(v.w);
                l.x = to_tf32(v.x - h.x); l.y = to_tf32(v.y - h.y);
                l.z = to_tf32(v.z - h.z); l.w = to_tf32(v.w - h.w);
                *(float4*)&sm[OFF_XHI + r * XSTRIDE + c4 * 4] = h;
                *(float4*)&sm[OFF_XLO + r * XSTRIDE + c4 * 4] = l;
            }
            // rowsq: one thread per row, round-1 order
            if (tid < MT) {
                const float4* xr = xb + tid * 16;
                float rowsq = 0.f;
                #pragma unroll
                for (int i = 0; i < 16; i++) {
                    float4 v = xr[i];
                    rowsq += ((v.x * v.x + v.y * v.y) + v.z * v.z) + v.w * v.w;
                }
                sm[OFF_RSQ + tid] = rowsq;
            }
            __syncthreads();

            // ---- per-warp: 16 rows x 256 codes via mma ----
            const int rowbase = wid * 16;
            const int r0 = rowbase + g, r1 = rowbase + 8 + g;

            float Ahi[32], Alo[32];
            #pragma unroll
            for (int s = 0; s < 8; s++) {
                Ahi[4*s+0] = sm[OFF_XHI + r0 * XSTRIDE + 8*s + tig];
                Ahi[4*s+1] = sm[OFF_XHI + r1 * XSTRIDE + 8*s + tig];
                Ahi[4*s+2] = sm[OFF_XHI + r0 * XSTRIDE + 8*s + tig + 4];
                Ahi[4*s+3] = sm[OFF_XHI + r1 * XSTRIDE + 8*s + tig + 4];
                Alo[4*s+0] = sm[OFF_XLO + r0 * XSTRIDE + 8*s + tig];
                Alo[4*s+1] = sm[OFF_XLO + r1 * XSTRIDE + 8*s + tig];
                Alo[4*s+2] = sm[OFF_XLO + r0 * XSTRIDE + 8*s + tig + 4];
                Alo[4*s+3] = sm[OFF_XLO + r1 * XSTRIDE + 8*s + tig + 4];
            }
            const float rs0 = sm[OFF_RSQ + r0];
            const float rs1 = sm[OFF_RSQ + r1];

            const int gr0 = t * MT + r0, gr1 = t * MT + r1;
            float best0, best1; int bk0, bk1;
            if (phase == 0) {
                best0 = CUDART_INF_F; bk0 = 0;
                best1 = CUDART_INF_F; bk1 = 0;
            } else {
                best0 = g_best[gr0]; bk0 = g_bestk[gr0];
                best1 = g_best[gr1]; bk1 = g_bestk[gr1];
            }

            #pragma unroll 2
            for (int n = 0; n < CHUNKS; n++) {
                float4 BH[4], BL[4];
                #pragma unroll
                for (int s2 = 0; s2 < 4; s2++) {
                    BH[s2] = EH4[(n * 4 + s2) * 32 + lane];
                    BL[s2] = EL4[(n * 4 + s2) * 32 + lane];
                }
                float hh0=0.f,hh1=0.f,hh2=0.f,hh3=0.f;
                float hl0=0.f,hl1=0.f,hl2=0.f,hl3=0.f;
                float lh0=0.f,lh1=0.f,lh2=0.f,lh3=0.f;
                #pragma unroll
                for (int s = 0; s < 8; s++) {
                    const float bh0 = (s & 1) ? BH[s>>1].z : BH[s>>1].x;
                    const float bh1 = (s & 1) ? BH[s>>1].w : BH[s>>1].y;
                    const float bl0 = (s & 1) ? BL[s>>1].z : BL[s>>1].x;
                    const float bl1 = (s & 1) ? BL[s>>1].w : BL[s>>1].y;
                    mma_tf32(hh0,hh1,hh2,hh3, Ahi[4*s],Ahi[4*s+1],Ahi[4*s+2],Ahi[4*s+3], bh0,bh1);
                    mma_tf32(hl0,hl1,hl2,hl3, Ahi[4*s],Ahi[4*s+1],Ahi[4*s+2],Ahi[4*s+3], bl0,bl1);
                    mma_tf32(lh0,lh1,lh2,lh3, Alo[4*s],Alo[4*s+1],Alo[4*s+2],Alo[4*s+3], bh0,bh1);
                }
                const float d00 = (hh0 + hl0) + lh0;
                const float d01 = (hh1 + hl1) + lh1;
                const float d10 = (hh2 + hl2) + lh2;
                const float d11 = (hh3 + hl3) + lh3;

                const float2 nv = *(const float2*)&sm[OFF_NRM + n * 8 + 2 * tig];
                const int k0 = kb + n * 8 + 2 * tig;
                const float s00 = (rs0 + nv.x) - 2.0f * d00;
                const float s01 = (rs0 + nv.y) - 2.0f * d01;
                const float s10 = (rs1 + nv.x) - 2.0f * d10;
                const float s11 = (rs1 + nv.y) - 2.0f * d11;
                if (s00 < best0) { best0 = s00; bk0 = k0; }
                if (s01 < best0) { best0 = s01; bk0 = k0 + 1; }
                if (s10 < best1) { best1 = s10; bk1 = k0; }
                if (s11 < best1) { best1 = s11; bk1 = k0 + 1; }
            }

            // cross-lane merge over the 4 tig lanes (tie -> lowest k)
            #pragma unroll
            for (int off = 1; off <= 2; off <<= 1) {
                float os0 = __shfl_xor_sync(0xffffffffu, best0, off);
                int   ok0 = __shfl_xor_sync(0xffffffffu, bk0,   off);
                float os1 = __shfl_xor_sync(0xffffffffu, best1, off);
                int   ok1 = __shfl_xor_sync(0xffffffffu, bk1,   off);
                if (os0 < best0 || (os0 == best0 && ok0 < bk0)) { best0 = os0; bk0 = ok0; }
                if (os1 < best1 || (os1 == best1 && ok1 < bk1)) { best1 = os1; bk1 = ok1; }
            }
            if (tig == 0) {
                if (phase == 0) {
                    g_best[gr0] = best0; g_bestk[gr0] = bk0;
                    g_best[gr1] = best1; g_bestk[gr1] = bk1;
                } else {
                    sm[OFF_BEST + r0] = best0; sBk[r0] = bk0;
                    sm[OFF_BEST + r1] = best1; sBk[r1] = bk1;
                }
            }
            __syncthreads();

            if (phase == 1) {
                // gather + coalesced write of quantized rows
                float4* o4 = (float4*)(out + (size_t)t * (MT * D));
                const float4* e4 = (const float4*)emb;
                #pragma unroll
                for (int i4 = tid; i4 < MT * D / 4; i4 += TPB) {
                    const int r = i4 >> 4, dd = i4 & 15;
                    o4[i4] = e4[(size_t)sBk[r] * 16 + dd];
                }
                if (tid < MT) {
                    float v = sm[OFF_BEST + tid];
                    #pragma unroll
                    for (int off = 16; off > 0; off >>= 1)
                        v += __shfl_down_sync(0xffffffffu, v, off);
                    if ((tid & 31) == 0) sm[OFF_WSUM + (tid >> 5)] = v;
                }
            }
            __syncthreads();
            if (phase == 1 && tid == 0)
                ctaAcc += ((sm[OFF_WSUM] + sm[OFF_WSUM+1]) + sm[OFF_WSUM+2]) + sm[OFF_WSUM+3];
        }
        __syncthreads();   // before Epack is rebuilt for next phase
    }

    if (tid == 0) g_cta[blockIdx.x] = ctaAcc;
}

__global__ void vq_finalize(float* __restrict__ out, int out_size) {
    if (threadIdx.x == 0) {
        float s = 0.f;
        for (int i = 0; i < GRID; i++) s += g_cta[i];
        float mean = s / (float)((long long)NROWS * D);
        out[out_size - 2] = mean;          // codebook_loss
        out[out_size - 1] = 0.25f * mean;  // commitment_loss (BETA = 0.25)
    }
}

extern "C" void kernel_launch(void* const* d_in, const int* in_sizes, int n_in,
                              void* d_out, int out_size) {
    const float* x   = (const float*)d_in[0];   // inputs (B,H,W,D) f32
    const float* emb = (const float*)d_in[1];   // embeddings (K,D) f32
    float* out = (float*)d_out;

    cudaFuncSetAttribute(vq_main, cudaFuncAttributeMaxDynamicSharedMemorySize,
                         SM_BYTES);
    vq_main<<<GRID, TPB, SM_BYTES>>>(x, emb, out);
    vq_finalize<<<1, 32>>>(out, out_size);
}